// round 7
// baseline (speedup 1.0000x reference)
#include <cuda_runtime.h>
#include <cuda_bf16.h>
#include <cstdint>

#define BATCH 16
#define SEQ   2048
#define DIM   128
#define TI    64
#define TJ    32
#define NTI   (SEQ/TI)            // 32 i-tiles
#define SCALE 0.088388347648318447f

// smem byte offsets (XOR-swizzled tiles, 256B per 128-col bf16 row, no padding)
#define SK_HI 0
#define SK_LO 16384
#define SQ_HI 32768
#define SQ_LO 40960
#define SV_HI 49152
#define SV_LO 57344
#define SSL   65536               // 64 floats row sums
#define SMEM_BYTES (65536 + 256)

__device__ __forceinline__ uint32_t smem_u32(const void* p) {
    uint32_t a;
    asm("{ .reg .u64 t; cvta.to.shared.u64 t, %1; cvt.u32.u64 %0, t; }" : "=r"(a) : "l"(p));
    return a;
}

// byte offset of (row, colElem) in a [rows x 128] bf16 tile, swizzled for
// conflict-free ldmatrix: XOR 16B-chunk index bits [6:4] with row[2:0]
__device__ __forceinline__ uint32_t swz(int row, int col) {
    uint32_t byte = ((uint32_t)row << 8) + ((uint32_t)col << 1);
    return byte ^ (((uint32_t)row & 7u) << 4);
}

__device__ __forceinline__ void ldsm4(uint32_t* r, uint32_t addr) {
    asm volatile("ldmatrix.sync.aligned.m8n8.x4.shared.b16 {%0,%1,%2,%3}, [%4];"
                 : "=r"(r[0]), "=r"(r[1]), "=r"(r[2]), "=r"(r[3]) : "r"(addr));
}
__device__ __forceinline__ void ldsm4t(uint32_t* r, uint32_t addr) {
    asm volatile("ldmatrix.sync.aligned.m8n8.x4.trans.shared.b16 {%0,%1,%2,%3}, [%4];"
                 : "=r"(r[0]), "=r"(r[1]), "=r"(r[2]), "=r"(r[3]) : "r"(addr));
}
__device__ __forceinline__ void mma16816(float* d, const uint32_t* a, const uint32_t* b) {
    asm volatile("mma.sync.aligned.m16n8k16.row.col.f32.bf16.bf16.f32 "
                 "{%0,%1,%2,%3}, {%4,%5,%6,%7}, {%8,%9}, {%0,%1,%2,%3};"
                 : "+f"(d[0]), "+f"(d[1]), "+f"(d[2]), "+f"(d[3])
                 : "r"(a[0]), "r"(a[1]), "r"(a[2]), "r"(a[3]), "r"(b[0]), "r"(b[1]));
}

__device__ __forceinline__ uint32_t pack_bf2(float a, float b) {
    __nv_bfloat162 t = __floats2bfloat162_rn(a, b);
    return *(uint32_t*)&t;
}

// split float4 to bf16 hi/lo; store 4 elems at swizzled (row, col), col % 4 == 0
__device__ __forceinline__ void split_store(char* smem, int off_hi, int off_lo,
                                            int row, int col, float4 v) {
    __nv_bfloat162 h0 = __floats2bfloat162_rn(v.x, v.y);
    __nv_bfloat162 h1 = __floats2bfloat162_rn(v.z, v.w);
    __nv_bfloat162 l0 = __floats2bfloat162_rn(v.x - __bfloat162float(h0.x),
                                              v.y - __bfloat162float(h0.y));
    __nv_bfloat162 l1 = __floats2bfloat162_rn(v.z - __bfloat162float(h1.x),
                                              v.w - __bfloat162float(h1.y));
    uint2 hh, ll;
    hh.x = *(uint32_t*)&h0; hh.y = *(uint32_t*)&h1;
    ll.x = *(uint32_t*)&l0; ll.y = *(uint32_t*)&l1;
    const uint32_t o = swz(row, col);
    *(uint2*)(smem + off_hi + o) = hh;
    *(uint2*)(smem + off_lo + o) = ll;
}

__global__ __launch_bounds__(128, 3)
void attn_mma_kernel(const float* __restrict__ Q, const float* __restrict__ K,
                     const float* __restrict__ V, float* __restrict__ outp,
                     float* __restrict__ wts) {
    extern __shared__ __align__(16) char smem[];
    float* sL = (float*)(smem + SSL);
    const uint32_t su = smem_u32(smem);

    const int tid = threadIdx.x;
    const int wid = tid >> 5;               // 0..3
    const int l   = tid & 31;
    const int m0  = wid * 16;
    const int cpair = blockIdx.x;           // 0..15
    const int b   = blockIdx.y;

    const int g   = l >> 3, r = l & 7;
    const int gb0 = g & 1, gb1 = g >> 1;
    const int ar  = l >> 2, ac = l & 3;

    #pragma unroll 1
    for (int ph = 0; ph < 2; ph++) {
        const int it = ph ? (NTI - 1 - cpair) : cpair;
        const int i0 = it * TI;
        const int gi0 = i0 + m0 + ar;

        __syncthreads();   // smem reuse across phases

        // ---- load + split K tile (64 rows, persistent) ----
        {
            const int row = tid >> 1, seg = (tid & 1) * 64;
            const float4* src = (const float4*)(K + ((size_t)(b * SEQ + i0 + row)) * DIM + seg);
            #pragma unroll
            for (int c = 0; c < 16; c++)
                split_store(smem, SK_HI, SK_LO, row, seg + c * 4, src[c]);
        }

        // ---- zero-fill lower-triangle cols [0, i0) ----
        {
            const int W0 = i0 / 4;
            const float4 z4 = make_float4(0.0f, 0.0f, 0.0f, 0.0f);
            for (int row = wid; row < TI; row += 4) {
                float4* wr = (float4*)(wts + ((size_t)(b * SEQ + i0 + row)) * SEQ);
                for (int q = l; q < W0; q += 32) wr[q] = z4;
            }
        }

        float Oa[16][4];
        #pragma unroll
        for (int nb = 0; nb < 16; nb++)
            #pragma unroll
            for (int e = 0; e < 4; e++) Oa[nb][e] = 0.0f;
        float ls0 = 0.0f, ls1 = 0.0f;

        #pragma unroll 1
        for (int j0 = i0; j0 < SEQ; j0 += TJ) {
            __syncthreads();   // prev iter smem reads done

            // ---- load + split Q, V (32 rows each) ----
            {
                const int row = tid >> 2, seg = (tid & 3) * 32;
                const float4* qs = (const float4*)(Q + ((size_t)(b * SEQ + j0 + row)) * DIM + seg);
                const float4* vs = (const float4*)(V + ((size_t)(b * SEQ + j0 + row)) * DIM + seg);
                #pragma unroll
                for (int c = 0; c < 8; c++) {
                    split_store(smem, SQ_HI, SQ_LO, row, seg + c * 4, qs[c]);
                    split_store(smem, SV_HI, SV_LO, row, seg + c * 4, vs[c]);
                }
            }
            __syncthreads();

            // ---- MMA1: S(16x32) = Khi*Qhi + Klo*Qhi + Khi*Qlo ----
            float S[4][4];
            #pragma unroll
            for (int nb = 0; nb < 4; nb++)
                #pragma unroll
                for (int e = 0; e < 4; e++) S[nb][e] = 0.0f;

            #pragma unroll
            for (int ks = 0; ks < 8; ks++) {
                uint32_t ah[4], al[4];
                const uint32_t aoff = swz(m0 + gb0 * 8 + r, ks * 16 + gb1 * 8);
                ldsm4(ah, su + SK_HI + aoff);
                ldsm4(al, su + SK_LO + aoff);
                #pragma unroll
                for (int nbp = 0; nbp < 2; nbp++) {
                    uint32_t bh[4], bl[4];
                    const uint32_t boff = swz(nbp * 16 + gb1 * 8 + r, ks * 16 + gb0 * 8);
                    ldsm4(bh, su + SQ_HI + boff);
                    ldsm4(bl, su + SQ_LO + boff);
                    mma16816(S[2 * nbp],     ah, bh);
                    mma16816(S[2 * nbp + 1], ah, bh + 2);
                    mma16816(S[2 * nbp],     al, bh);
                    mma16816(S[2 * nbp + 1], al, bh + 2);
                    mma16816(S[2 * nbp],     ah, bl);
                    mma16816(S[2 * nbp + 1], ah, bl + 2);
                }
            }

            // ---- epilogue: exp, mask, write weights, P fragments in regs ----
            const bool maskp = (j0 < i0 + TI);
            uint32_t aPh[2][4], aPl[2][4];
            float* wr0 = wts + ((size_t)(b * SEQ + gi0)) * SEQ + j0 + 2 * ac;
            float* wr1 = wr0 + (size_t)8 * SEQ;
            #pragma unroll
            for (int nb = 0; nb < 4; nb++) {
                float p0 = __expf(S[nb][0] * SCALE);
                float p1 = __expf(S[nb][1] * SCALE);
                float p2 = __expf(S[nb][2] * SCALE);
                float p3 = __expf(S[nb][3] * SCALE);
                const int j = j0 + nb * 8 + 2 * ac;
                if (maskp) {
                    if (j     < gi0)     p0 = 0.0f;
                    if (j + 1 < gi0)     p1 = 0.0f;
                    if (j     < gi0 + 8) p2 = 0.0f;
                    if (j + 1 < gi0 + 8) p3 = 0.0f;
                }
                ls0 += p0 + p1;
                ls1 += p2 + p3;
                *(float2*)(wr0 + nb * 8) = make_float2(p0, p1);
                *(float2*)(wr1 + nb * 8) = make_float2(p2, p3);
                const uint32_t h01 = pack_bf2(p0, p1);
                const uint32_t h23 = pack_bf2(p2, p3);
                __nv_bfloat162 hh01 = *(__nv_bfloat162*)&h01;
                __nv_bfloat162 hh23 = *(__nv_bfloat162*)&h23;
                const uint32_t l01 = pack_bf2(p0 - __bfloat162float(hh01.x),
                                              p1 - __bfloat162float(hh01.y));
                const uint32_t l23 = pack_bf2(p2 - __bfloat162float(hh23.x),
                                              p3 - __bfloat162float(hh23.y));
                const int kb = nb >> 1, s = (nb & 1) * 2;
                aPh[kb][s]     = h01;
                aPh[kb][s + 1] = h23;
                aPl[kb][s]     = l01;
                aPl[kb][s + 1] = l23;
            }

            // ---- MMA2: O(16x128) += Phi*Vhi + Plo*Vhi + Phi*Vlo ----
            #pragma unroll
            for (int kb = 0; kb < 2; kb++) {
                #pragma unroll
                for (int dbp = 0; dbp < 8; dbp++) {
                    uint32_t bh[4], bl[4];
                    const uint32_t voff = swz(kb * 16 + gb0 * 8 + r, dbp * 16 + gb1 * 8);
                    ldsm4t(bh, su + SV_HI + voff);
                    ldsm4t(bl, su + SV_LO + voff);
                    mma16816(Oa[2 * dbp],     aPh[kb], bh);
                    mma16816(Oa[2 * dbp + 1], aPh[kb], bh + 2);
                    mma16816(Oa[2 * dbp],     aPl[kb], bh);
                    mma16816(Oa[2 * dbp + 1], aPl[kb], bh + 2);
                    mma16816(Oa[2 * dbp],     aPh[kb], bl);
                    mma16816(Oa[2 * dbp + 1], aPh[kb], bl + 2);
                }
            }
        }

        // ---- row sums: reduce over ac lanes (warp owns full row) ----
        ls0 += __shfl_xor_sync(0xffffffffu, ls0, 1);
        ls0 += __shfl_xor_sync(0xffffffffu, ls0, 2);
        ls1 += __shfl_xor_sync(0xffffffffu, ls1, 1);
        ls1 += __shfl_xor_sync(0xffffffffu, ls1, 2);
        const float inv0 = 1.0f / ls0;
        const float inv1 = 1.0f / ls1;

        // ---- store normalized O ----
        float* or0 = outp + ((size_t)(b * SEQ + gi0)) * DIM + 2 * ac;
        float* or1 = or0 + 8 * DIM;
        #pragma unroll
        for (int nb = 0; nb < 16; nb++) {
            const int col = (nb >> 1) * 16 + (nb & 1) * 8;
            *(float2*)(or0 + col) = make_float2(Oa[nb][0] * inv0, Oa[nb][1] * inv0);
            *(float2*)(or1 + col) = make_float2(Oa[nb][2] * inv1, Oa[nb][3] * inv1);
        }
        if (ac == 0) {
            sL[m0 + ar]     = ls0;
            sL[m0 + ar + 8] = ls1;
        }
        __syncthreads();

        // ---- in-kernel finalize: rescale own rows, cols [i0, SEQ) ----
        {
            const int W1 = (SEQ - i0) / 4;
            for (int row = wid; row < TI; row += 4) {
                const float inv = 1.0f / sL[row];
                float4* wr = (float4*)(wts + ((size_t)(b * SEQ + i0 + row)) * SEQ + i0);
                for (int q = l; q < W1; q += 32) {
                    float4 w = wr[q];
                    w.x *= inv; w.y *= inv; w.z *= inv; w.w *= inv;
                    wr[q] = w;
                }
            }
        }
    }
}

extern "C" void kernel_launch(void* const* d_in, const int* in_sizes, int n_in,
                              void* d_out, int out_size) {
    const float* Q = (const float*)d_in[0];
    const float* K = (const float*)d_in[1];
    const float* V = (const float*)d_in[2];
    float* outp = (float*)d_out;
    float* wts  = outp + (size_t)BATCH * SEQ * DIM;   // tuple: (outputs, weights)

    cudaFuncSetAttribute(attn_mma_kernel,
                         cudaFuncAttributeMaxDynamicSharedMemorySize, SMEM_BYTES);

    dim3 grid(NTI / 2, BATCH);
    attn_mma_kernel<<<grid, 128, SMEM_BYTES>>>(Q, K, V, outp, wts);
}

// round 8
// speedup vs baseline: 1.0972x; 1.0972x over previous
#include <cuda_runtime.h>
#include <cuda_bf16.h>
#include <cstdint>

#define BATCH 16
#define SEQ   2048
#define DIM   128
#define TI    64
#define TJ    64
#define NTI   (SEQ/TI)            // 32 i-tiles
#define SCALE 0.088388347648318447f

// smem byte offsets: 64x128 bf16 tiles (16KB), XOR-swizzled, no padding
#define SK_HI 0
#define SK_LO 16384
#define SQ_HI 32768               /* reused as P_hi staging after MMA1 */
#define SQ_LO 49152               /* reused as P_lo staging after MMA1 */
#define SV_HI 65536
#define SV_LO 81920
#define SSL   98304               // 2 x 64 floats row sums
#define SMEM_BYTES (98304 + 512)

__device__ __forceinline__ uint32_t smem_u32(const void* p) {
    uint32_t a;
    asm("{ .reg .u64 t; cvta.to.shared.u64 t, %1; cvt.u32.u64 %0, t; }" : "=r"(a) : "l"(p));
    return a;
}

// byte offset of (row, colElem) in a [rows x 128] bf16 tile (256B rows),
// swizzled: XOR 16B-chunk bits [6:4] with row[2:0] -> conflict-free ldmatrix
__device__ __forceinline__ uint32_t swz(int row, int col) {
    uint32_t byte = ((uint32_t)row << 8) + ((uint32_t)col << 1);
    return byte ^ (((uint32_t)row & 7u) << 4);
}

__device__ __forceinline__ void ldsm4(uint32_t* r, uint32_t addr) {
    asm volatile("ldmatrix.sync.aligned.m8n8.x4.shared.b16 {%0,%1,%2,%3}, [%4];"
                 : "=r"(r[0]), "=r"(r[1]), "=r"(r[2]), "=r"(r[3]) : "r"(addr));
}
__device__ __forceinline__ void ldsm4t(uint32_t* r, uint32_t addr) {
    asm volatile("ldmatrix.sync.aligned.m8n8.x4.trans.shared.b16 {%0,%1,%2,%3}, [%4];"
                 : "=r"(r[0]), "=r"(r[1]), "=r"(r[2]), "=r"(r[3]) : "r"(addr));
}
__device__ __forceinline__ void mma16816(float* d, const uint32_t* a, const uint32_t* b) {
    asm volatile("mma.sync.aligned.m16n8k16.row.col.f32.bf16.bf16.f32 "
                 "{%0,%1,%2,%3}, {%4,%5,%6,%7}, {%8,%9}, {%0,%1,%2,%3};"
                 : "+f"(d[0]), "+f"(d[1]), "+f"(d[2]), "+f"(d[3])
                 : "r"(a[0]), "r"(a[1]), "r"(a[2]), "r"(a[3]), "r"(b[0]), "r"(b[1]));
}

__device__ __forceinline__ uint32_t pack_bf2(float a, float b) {
    __nv_bfloat162 t = __floats2bfloat162_rn(a, b);
    return *(uint32_t*)&t;
}

// split float4 to bf16 hi/lo; store 4 elems at swizzled (row, col), col % 4 == 0
__device__ __forceinline__ void split_store(char* smem, int off_hi, int off_lo,
                                            int row, int col, float4 v) {
    __nv_bfloat162 h0 = __floats2bfloat162_rn(v.x, v.y);
    __nv_bfloat162 h1 = __floats2bfloat162_rn(v.z, v.w);
    __nv_bfloat162 l0 = __floats2bfloat162_rn(v.x - __bfloat162float(h0.x),
                                              v.y - __bfloat162float(h0.y));
    __nv_bfloat162 l1 = __floats2bfloat162_rn(v.z - __bfloat162float(h1.x),
                                              v.w - __bfloat162float(h1.y));
    uint2 hh, ll;
    hh.x = *(uint32_t*)&h0; hh.y = *(uint32_t*)&h1;
    ll.x = *(uint32_t*)&l0; ll.y = *(uint32_t*)&l1;
    const uint32_t o = swz(row, col);
    *(uint2*)(smem + off_hi + o) = hh;
    *(uint2*)(smem + off_lo + o) = ll;
}

__global__ __launch_bounds__(256, 2)
void attn_mma_kernel(const float* __restrict__ Q, const float* __restrict__ K,
                     const float* __restrict__ V, float* __restrict__ outp,
                     float* __restrict__ wts) {
    extern __shared__ __align__(16) char smem[];
    float* sL = (float*)(smem + SSL);       // [2][64] per-half row sums
    const uint32_t su = smem_u32(smem);

    const int tid = threadIdx.x;
    const int wid = tid >> 5;               // 0..7
    const int l   = tid & 31;
    const int m   = wid & 3;                // row-block (16 rows)
    const int h   = wid >> 2;               // col/d half
    const int m0  = m * 16;
    const int cpair = blockIdx.x;           // 0..15
    const int b   = blockIdx.y;

    const int g   = l >> 3, r = l & 7;
    const int gb0 = g & 1, gb1 = g >> 1;
    const int ar  = l >> 2, ac = l & 3;

    #pragma unroll 1
    for (int ph = 0; ph < 2; ph++) {
        const int it = ph ? (NTI - 1 - cpair) : cpair;
        const int i0 = it * TI;
        const int gi0 = i0 + m0 + ar;

        __syncthreads();   // smem reuse across phases

        // ---- load + split K tile (64 rows, persistent) ----
        {
            const int row = tid >> 2, seg = (tid & 3) * 32;
            const float4* src = (const float4*)(K + ((size_t)(b * SEQ + i0 + row)) * DIM + seg);
            #pragma unroll
            for (int c = 0; c < 8; c++)
                split_store(smem, SK_HI, SK_LO, row, seg + c * 4, src[c]);
        }

        // ---- zero-fill lower-triangle cols [0, i0) ----
        {
            const int W0 = i0 / 4;
            const float4 z4 = make_float4(0.0f, 0.0f, 0.0f, 0.0f);
            for (int row = wid; row < TI; row += 8) {
                float4* wr = (float4*)(wts + ((size_t)(b * SEQ + i0 + row)) * SEQ);
                for (int q = l; q < W0; q += 32) wr[q] = z4;
            }
        }

        float Oa[8][4];
        #pragma unroll
        for (int nb = 0; nb < 8; nb++)
            #pragma unroll
            for (int e = 0; e < 4; e++) Oa[nb][e] = 0.0f;
        float ls0 = 0.0f, ls1 = 0.0f;

        #pragma unroll 1
        for (int j0 = i0; j0 < SEQ; j0 += TJ) {
            __syncthreads();   // prev iter smem reads done

            // ---- load + split Q, V (64 rows each) ----
            {
                const int row = tid >> 2, seg = (tid & 3) * 32;
                const float4* qs = (const float4*)(Q + ((size_t)(b * SEQ + j0 + row)) * DIM + seg);
                const float4* vs = (const float4*)(V + ((size_t)(b * SEQ + j0 + row)) * DIM + seg);
                #pragma unroll
                for (int c = 0; c < 8; c++) {
                    split_store(smem, SQ_HI, SQ_LO, row, seg + c * 4, qs[c]);
                    split_store(smem, SV_HI, SV_LO, row, seg + c * 4, vs[c]);
                }
            }
            __syncthreads();

            // ---- MMA1: S(16x32 half) = Khi*Qhi + Klo*Qhi + Khi*Qlo ----
            float S[4][4];
            #pragma unroll
            for (int nb = 0; nb < 4; nb++)
                #pragma unroll
                for (int e = 0; e < 4; e++) S[nb][e] = 0.0f;

            #pragma unroll
            for (int ks = 0; ks < 8; ks++) {
                uint32_t ah[4], al[4];
                const uint32_t aoff = swz(m0 + gb0 * 8 + r, ks * 16 + gb1 * 8);
                ldsm4(ah, su + SK_HI + aoff);
                ldsm4(al, su + SK_LO + aoff);
                #pragma unroll
                for (int nbp = 0; nbp < 2; nbp++) {
                    uint32_t bh[4], bl[4];
                    const uint32_t boff = swz(h * 32 + nbp * 16 + gb1 * 8 + r, ks * 16 + gb0 * 8);
                    ldsm4(bh, su + SQ_HI + boff);
                    ldsm4(bl, su + SQ_LO + boff);
                    mma16816(S[2 * nbp],     ah, bh);
                    mma16816(S[2 * nbp + 1], ah, bh + 2);
                    mma16816(S[2 * nbp],     al, bh);
                    mma16816(S[2 * nbp + 1], al, bh + 2);
                    mma16816(S[2 * nbp],     ah, bl);
                    mma16816(S[2 * nbp + 1], ah, bl + 2);
                }
            }
            __syncthreads();   // MMA1 Q-reads done before P staging overwrites

            // ---- epilogue: exp, mask, write weights, stage P into Q smem ----
            const bool maskp = (j0 == i0);
            const int cb = h * 32 + 2 * ac;
            float* wr0 = wts + ((size_t)(b * SEQ + gi0)) * SEQ + j0 + cb;
            float* wr1 = wr0 + (size_t)8 * SEQ;
            #pragma unroll
            for (int nb = 0; nb < 4; nb++) {
                float p0 = __expf(S[nb][0] * SCALE);
                float p1 = __expf(S[nb][1] * SCALE);
                float p2 = __expf(S[nb][2] * SCALE);
                float p3 = __expf(S[nb][3] * SCALE);
                const int j = j0 + cb + nb * 8;
                if (maskp) {
                    if (j     < gi0)     p0 = 0.0f;
                    if (j + 1 < gi0)     p1 = 0.0f;
                    if (j     < gi0 + 8) p2 = 0.0f;
                    if (j + 1 < gi0 + 8) p3 = 0.0f;
                }
                ls0 += p0 + p1;
                ls1 += p2 + p3;
                *(float2*)(wr0 + nb * 8) = make_float2(p0, p1);
                *(float2*)(wr1 + nb * 8) = make_float2(p2, p3);
                const uint32_t h01 = pack_bf2(p0, p1);
                const uint32_t h23 = pack_bf2(p2, p3);
                __nv_bfloat162 hh01 = *(__nv_bfloat162*)&h01;
                __nv_bfloat162 hh23 = *(__nv_bfloat162*)&h23;
                const uint32_t l01 = pack_bf2(p0 - __bfloat162float(hh01.x),
                                              p1 - __bfloat162float(hh01.y));
                const uint32_t l23 = pack_bf2(p2 - __bfloat162float(hh23.x),
                                              p3 - __bfloat162float(hh23.y));
                const uint32_t o0 = swz(m0 + ar,     cb + nb * 8);
                const uint32_t o1 = swz(m0 + ar + 8, cb + nb * 8);
                *(uint32_t*)(smem + SQ_HI + o0) = h01;
                *(uint32_t*)(smem + SQ_HI + o1) = h23;
                *(uint32_t*)(smem + SQ_LO + o0) = l01;
                *(uint32_t*)(smem + SQ_LO + o1) = l23;
            }
            __syncthreads();   // P staged; both halves visible

            // ---- MMA2: O(16 x 64 d-half) += Phi*Vhi + Plo*Vhi + Phi*Vlo ----
            #pragma unroll
            for (int kb = 0; kb < 4; kb++) {
                uint32_t aPh[4], aPl[4];
                const uint32_t poff = swz(m0 + gb0 * 8 + r, kb * 16 + gb1 * 8);
                ldsm4(aPh, su + SQ_HI + poff);
                ldsm4(aPl, su + SQ_LO + poff);
                #pragma unroll
                for (int dbp = 0; dbp < 4; dbp++) {
                    uint32_t bh[4], bl[4];
                    const uint32_t voff = swz(kb * 16 + gb0 * 8 + r, h * 64 + dbp * 16 + gb1 * 8);
                    ldsm4t(bh, su + SV_HI + voff);
                    ldsm4t(bl, su + SV_LO + voff);
                    mma16816(Oa[2 * dbp],     aPh, bh);
                    mma16816(Oa[2 * dbp + 1], aPh, bh + 2);
                    mma16816(Oa[2 * dbp],     aPl, bh);
                    mma16816(Oa[2 * dbp + 1], aPl, bh + 2);
                    mma16816(Oa[2 * dbp],     aPh, bl);
                    mma16816(Oa[2 * dbp + 1], aPh, bl + 2);
                }
            }
        }

        // ---- reduce half-row sums across ac lanes, publish to smem ----
        ls0 += __shfl_xor_sync(0xffffffffu, ls0, 1);
        ls0 += __shfl_xor_sync(0xffffffffu, ls0, 2);
        ls1 += __shfl_xor_sync(0xffffffffu, ls1, 1);
        ls1 += __shfl_xor_sync(0xffffffffu, ls1, 2);
        if (ac == 0) {
            sL[h * 64 + m0 + ar]     = ls0;
            sL[h * 64 + m0 + ar + 8] = ls1;
        }
        __syncthreads();

        const float tot0 = sL[m0 + ar]     + sL[64 + m0 + ar];
        const float tot1 = sL[m0 + ar + 8] + sL[64 + m0 + ar + 8];
        const float inv0 = 1.0f / tot0;
        const float inv1 = 1.0f / tot1;

        // ---- store normalized O (this warp's d-half) ----
        float* or0 = outp + ((size_t)(b * SEQ + gi0)) * DIM + h * 64 + 2 * ac;
        float* or1 = or0 + 8 * DIM;
        #pragma unroll
        for (int nb = 0; nb < 8; nb++) {
            const int col = (nb >> 1) * 16 + (nb & 1) * 8;
            *(float2*)(or0 + col) = make_float2(Oa[nb][0] * inv0, Oa[nb][1] * inv0);
            *(float2*)(or1 + col) = make_float2(Oa[nb][2] * inv1, Oa[nb][3] * inv1);
        }

        // ---- in-kernel finalize: rescale own rows, cols [i0, SEQ) ----
        {
            const int W1 = (SEQ - i0) / 4;
            for (int row = wid; row < TI; row += 8) {
                const float inv = 1.0f / (sL[row] + sL[64 + row]);
                float4* wr = (float4*)(wts + ((size_t)(b * SEQ + i0 + row)) * SEQ + i0);
                for (int q = l; q < W1; q += 32) {
                    float4 w = wr[q];
                    w.x *= inv; w.y *= inv; w.z *= inv; w.w *= inv;
                    wr[q] = w;
                }
            }
        }
    }
}

extern "C" void kernel_launch(void* const* d_in, const int* in_sizes, int n_in,
                              void* d_out, int out_size) {
    const float* Q = (const float*)d_in[0];
    const float* K = (const float*)d_in[1];
    const float* V = (const float*)d_in[2];
    float* outp = (float*)d_out;
    float* wts  = outp + (size_t)BATCH * SEQ * DIM;   // tuple: (outputs, weights)

    cudaFuncSetAttribute(attn_mma_kernel,
                         cudaFuncAttributeMaxDynamicSharedMemorySize, SMEM_BYTES);

    dim3 grid(NTI / 2, BATCH);
    attn_mma_kernel<<<grid, 256, SMEM_BYTES>>>(Q, K, V, outp, wts);
}

// round 10
// speedup vs baseline: 1.5981x; 1.4565x over previous
#include <cuda_runtime.h>
#include <cuda_bf16.h>
#include <cstdint>

#define BATCH 16
#define SEQ   2048
#define DIM   128
#define TILE  128
#define NT    (SEQ/TILE)
#define SCALE 0.088388347648318447f
#define LDE   136                 // bf16 elements per padded smem row
#define NELEM (BATCH*SEQ*DIM)

#define T_ELEMS (TILE*LDE)
#define OFF_KHI 0
#define OFF_KLO (1*T_ELEMS)
#define OFF_QHI (2*T_ELEMS)      /* reused as P_hi staging after MMA1 */
#define OFF_QLO (3*T_ELEMS)      /* reused as P_lo staging after MMA1 */
#define OFF_VHI (4*T_ELEMS)
#define OFF_VLO (5*T_ELEMS)
#define OFF_SL  (6*T_ELEMS)      // 256 floats: per-half row sums
#define SMEM_BYTES (6*T_ELEMS*2 + 256*4)

// pre-split bf16 inputs: [0]=Q, [1]=K, [2]=V
static __device__ __nv_bfloat16 g_hi[3][NELEM];
static __device__ __nv_bfloat16 g_lo[3][NELEM];

__device__ __forceinline__ uint32_t smem_u32(const void* p) {
    uint32_t a;
    asm("{ .reg .u64 t; cvta.to.shared.u64 t, %1; cvt.u32.u64 %0, t; }" : "=r"(a) : "l"(p));
    return a;
}

__device__ __forceinline__ void cpa16(uint32_t dst, const void* src) {
    asm volatile("cp.async.cg.shared.global [%0], [%1], 16;" :: "r"(dst), "l"(src));
}
__device__ __forceinline__ void cpa_commit() {
    asm volatile("cp.async.commit_group;" ::: "memory");
}
__device__ __forceinline__ void cpa_wait_all() {
    asm volatile("cp.async.wait_group 0;" ::: "memory");
}

__device__ __forceinline__ void ldsm4(uint32_t* r, uint32_t addr) {
    asm volatile("ldmatrix.sync.aligned.m8n8.x4.shared.b16 {%0,%1,%2,%3}, [%4];"
                 : "=r"(r[0]), "=r"(r[1]), "=r"(r[2]), "=r"(r[3]) : "r"(addr));
}
__device__ __forceinline__ void ldsm4t(uint32_t* r, uint32_t addr) {
    asm volatile("ldmatrix.sync.aligned.m8n8.x4.trans.shared.b16 {%0,%1,%2,%3}, [%4];"
                 : "=r"(r[0]), "=r"(r[1]), "=r"(r[2]), "=r"(r[3]) : "r"(addr));
}
__device__ __forceinline__ void mma16816(float* d, const uint32_t* a, const uint32_t* b) {
    asm volatile("mma.sync.aligned.m16n8k16.row.col.f32.bf16.bf16.f32 "
                 "{%0,%1,%2,%3}, {%4,%5,%6,%7}, {%8,%9}, {%0,%1,%2,%3};"
                 : "+f"(d[0]), "+f"(d[1]), "+f"(d[2]), "+f"(d[3])
                 : "r"(a[0]), "r"(a[1]), "r"(a[2]), "r"(a[3]), "r"(b[0]), "r"(b[1]));
}

__device__ __forceinline__ uint32_t pack_bf2(float a, float b) {
    __nv_bfloat162 t = __floats2bfloat162_rn(a, b);
    return *(uint32_t*)&t;
}

// ---------------- pre-pass: split fp32 -> bf16 hi/lo ----------------
__global__ __launch_bounds__(256)
void split_pre_kernel(const float* __restrict__ Q, const float* __restrict__ K,
                      const float* __restrict__ V) {
    const int t = blockIdx.y;
    const float* X = (t == 0) ? Q : ((t == 1) ? K : V);
    const size_t i4 = (size_t)blockIdx.x * blockDim.x + threadIdx.x;
    const float4 v = ((const float4*)X)[i4];
    __nv_bfloat162 h0 = __floats2bfloat162_rn(v.x, v.y);
    __nv_bfloat162 h1 = __floats2bfloat162_rn(v.z, v.w);
    __nv_bfloat162 l0 = __floats2bfloat162_rn(v.x - __bfloat162float(h0.x),
                                              v.y - __bfloat162float(h0.y));
    __nv_bfloat162 l1 = __floats2bfloat162_rn(v.z - __bfloat162float(h1.x),
                                              v.w - __bfloat162float(h1.y));
    uint2 hh, ll;
    hh.x = *(uint32_t*)&h0; hh.y = *(uint32_t*)&h1;
    ll.x = *(uint32_t*)&l0; ll.y = *(uint32_t*)&l1;
    ((uint2*)g_hi[t])[i4] = hh;
    ((uint2*)g_lo[t])[i4] = ll;
}

// ---------------- main kernel (R5 structure, cp.async loads) ----------------
__global__ __launch_bounds__(512, 1)
void attn_mma_kernel(float* __restrict__ outp, float* __restrict__ wts) {
    extern __shared__ __align__(16) char smem_raw[];
    __nv_bfloat16* sb = (__nv_bfloat16*)smem_raw;
    float* sL = (float*)(sb + OFF_SL);      // [2][128] per-half row sums
    const uint32_t su = smem_u32(smem_raw);

    const int tid = threadIdx.x;
    const int wid = tid >> 5;               // 0..15
    const int l   = tid & 31;
    const int m   = wid & 7;                // row-block
    const int h   = wid >> 3;               // col/d half
    const int m0  = m * 16;
    const int cpair = blockIdx.x;           // 0..7
    const int b   = blockIdx.y;

    const int g   = l >> 3, r = l & 7;
    const int gb0 = g & 1, gb1 = g >> 1;
    const int ar  = l >> 2, ac = l & 3;

    const int offA = (m0 + gb0 * 8 + r) * LDE + gb1 * 8;    // A frags (K rows / P rows)
    const int offB = (gb1 * 8 + r) * LDE + gb0 * 8;         // B frags (Q rows)
    const int offV = (gb0 * 8 + r) * LDE + gb1 * 8;         // B frags (V rows, trans)

    // cp.async chunk decomposition: 2048 16B-chunks per 128x128 bf16 tile
    const int crow0 = tid >> 4;             // chunk rows: tid..tid+... (4 chunks/thread)
    const int ccol0 = (tid & 15) * 8;       // element col of 16B chunk

    #pragma unroll 1
    for (int ph = 0; ph < 2; ph++) {
        const int it = ph ? (NT - 1 - cpair) : cpair;
        const int i0 = it * TILE;
        const int gi0 = i0 + m0 + ar;

        __syncthreads();   // smem reuse across phases

        // ---- K tile via cp.async (pre-split bf16) ----
        {
            const size_t base = (size_t)(b * SEQ + i0) * DIM;
            #pragma unroll
            for (int i = 0; i < 4; i++) {
                const int row = crow0 + i * 32;
                const uint32_t ds = su + (uint32_t)((row * LDE + ccol0) << 1);
                const size_t gofs = base + (size_t)row * DIM + ccol0;
                cpa16(ds + (OFF_KHI << 1), g_hi[1] + gofs);
                cpa16(ds + (OFF_KLO << 1), g_lo[1] + gofs);
            }
            cpa_commit();
        }

        // ---- zero-fill lower-triangle cols [0, i0) (overlaps K loads) ----
        {
            const int W0 = i0 / 4;
            const float4 z4 = make_float4(0.0f, 0.0f, 0.0f, 0.0f);
            for (int row = wid; row < TILE; row += 16) {
                float4* wr = (float4*)(wts + ((size_t)(b * SEQ + i0 + row)) * SEQ);
                for (int q = l; q < W0; q += 32) wr[q] = z4;
            }
        }

        float Oa[8][4];
        #pragma unroll
        for (int nb = 0; nb < 8; nb++)
            #pragma unroll
            for (int e = 0; e < 4; e++) Oa[nb][e] = 0.0f;
        float ls0 = 0.0f, ls1 = 0.0f;

        #pragma unroll 1
        for (int jt = it; jt < NT; jt++) {
            const int j0 = jt * TILE;
            __syncthreads();   // prev iter smem readers done

            // ---- Q, V tiles via cp.async (pre-split bf16) ----
            {
                const size_t base = (size_t)(b * SEQ + j0) * DIM;
                #pragma unroll
                for (int i = 0; i < 4; i++) {
                    const int row = crow0 + i * 32;
                    const uint32_t ds = su + (uint32_t)((row * LDE + ccol0) << 1);
                    const size_t gofs = base + (size_t)row * DIM + ccol0;
                    cpa16(ds + (OFF_QHI << 1), g_hi[0] + gofs);
                    cpa16(ds + (OFF_QLO << 1), g_lo[0] + gofs);
                    cpa16(ds + (OFF_VHI << 1), g_hi[2] + gofs);
                    cpa16(ds + (OFF_VLO << 1), g_lo[2] + gofs);
                }
                cpa_commit();
                cpa_wait_all();
            }
            __syncthreads();

            // ---- MMA1: S = Khi*Qhi + Klo*Qhi + Khi*Qlo ----
            float S[8][4];
            #pragma unroll
            for (int nb = 0; nb < 8; nb++)
                #pragma unroll
                for (int e = 0; e < 4; e++) S[nb][e] = 0.0f;

            #pragma unroll
            for (int ks = 0; ks < 8; ks++) {
                uint32_t ah[4], al[4];
                ldsm4(ah, su + (uint32_t)((OFF_KHI + offA + ks * 16) << 1));
                ldsm4(al, su + (uint32_t)((OFF_KLO + offA + ks * 16) << 1));
                #pragma unroll
                for (int nbp = 0; nbp < 4; nbp++) {
                    const int nbg = h * 4 + nbp;
                    uint32_t bh[4], bl[4];
                    ldsm4(bh, su + (uint32_t)((OFF_QHI + offB + nbg * 16 * LDE + ks * 16) << 1));
                    ldsm4(bl, su + (uint32_t)((OFF_QLO + offB + nbg * 16 * LDE + ks * 16) << 1));
                    mma16816(S[2 * nbp],     ah, bh);
                    mma16816(S[2 * nbp + 1], ah, bh + 2);
                    mma16816(S[2 * nbp],     al, bh);
                    mma16816(S[2 * nbp + 1], al, bh + 2);
                    mma16816(S[2 * nbp],     ah, bl);
                    mma16816(S[2 * nbp + 1], ah, bl + 2);
                }
            }
            __syncthreads();   // Q reads done before P staging overwrites

            // ---- epilogue: exp, mask, STG weights, stage P into Q smem ----
            const bool diag = (jt == it);
            const int cb = h * 64 + 2 * ac;
            float* wr0 = wts + ((size_t)(b * SEQ + gi0)) * SEQ + j0 + cb;
            float* wr1 = wr0 + (size_t)8 * SEQ;
            #pragma unroll
            for (int nb = 0; nb < 8; nb++) {
                float p0 = __expf(S[nb][0] * SCALE);
                float p1 = __expf(S[nb][1] * SCALE);
                float p2 = __expf(S[nb][2] * SCALE);
                float p3 = __expf(S[nb][3] * SCALE);
                const int j = j0 + cb + nb * 8;
                if (diag) {
                    if (j     < gi0)     p0 = 0.0f;
                    if (j + 1 < gi0)     p1 = 0.0f;
                    if (j     < gi0 + 8) p2 = 0.0f;
                    if (j + 1 < gi0 + 8) p3 = 0.0f;
                }
                ls0 += p0 + p1;
                ls1 += p2 + p3;
                *(float2*)(wr0 + nb * 8) = make_float2(p0, p1);
                *(float2*)(wr1 + nb * 8) = make_float2(p2, p3);
                const uint32_t h01 = pack_bf2(p0, p1);
                const uint32_t h23 = pack_bf2(p2, p3);
                __nv_bfloat162 hh01 = *(__nv_bfloat162*)&h01;
                __nv_bfloat162 hh23 = *(__nv_bfloat162*)&h23;
                const uint32_t l01 = pack_bf2(p0 - __bfloat162float(hh01.x),
                                              p1 - __bfloat162float(hh01.y));
                const uint32_t l23 = pack_bf2(p2 - __bfloat162float(hh23.x),
                                              p3 - __bfloat162float(hh23.y));
                const int e0 = (m0 + ar) * LDE + cb + nb * 8;
                const int e1 = e0 + 8 * LDE;
                *(uint32_t*)(sb + OFF_QHI + e0) = h01;
                *(uint32_t*)(sb + OFF_QHI + e1) = h23;
                *(uint32_t*)(sb + OFF_QLO + e0) = l01;
                *(uint32_t*)(sb + OFF_QLO + e1) = l23;
            }
            __syncthreads();   // P staged; both halves visible

            // ---- MMA2: O += Phi*Vhi + Plo*Vhi + Phi*Vlo ----
            #pragma unroll
            for (int kb = 0; kb < 8; kb++) {
                uint32_t aPh[4], aPl[4];
                ldsm4(aPh, su + (uint32_t)((OFF_QHI + offA + kb * 16) << 1));
                ldsm4(aPl, su + (uint32_t)((OFF_QLO + offA + kb * 16) << 1));
                #pragma unroll
                for (int dbp = 0; dbp < 4; dbp++) {
                    const int dbg = h * 4 + dbp;
                    uint32_t bh[4], bl[4];
                    ldsm4t(bh, su + (uint32_t)((OFF_VHI + offV + kb * 16 * LDE + dbg * 16) << 1));
                    ldsm4t(bl, su + (uint32_t)((OFF_VLO + offV + kb * 16 * LDE + dbg * 16) << 1));
                    mma16816(Oa[2 * dbp],     aPh, bh);
                    mma16816(Oa[2 * dbp + 1], aPh, bh + 2);
                    mma16816(Oa[2 * dbp],     aPl, bh);
                    mma16816(Oa[2 * dbp + 1], aPl, bh + 2);
                    mma16816(Oa[2 * dbp],     aPh, bl);
                    mma16816(Oa[2 * dbp + 1], aPh, bl + 2);
                }
            }
        }

        // ---- reduce half-row sums across ac lanes, publish to smem ----
        ls0 += __shfl_xor_sync(0xffffffffu, ls0, 1);
        ls0 += __shfl_xor_sync(0xffffffffu, ls0, 2);
        ls1 += __shfl_xor_sync(0xffffffffu, ls1, 1);
        ls1 += __shfl_xor_sync(0xffffffffu, ls1, 2);
        if (ac == 0) {
            sL[h * 128 + m0 + ar]     = ls0;
            sL[h * 128 + m0 + ar + 8] = ls1;
        }
        __syncthreads();

        const float tot0 = sL[m0 + ar]     + sL[128 + m0 + ar];
        const float tot1 = sL[m0 + ar + 8] + sL[128 + m0 + ar + 8];
        const float inv0 = 1.0f / tot0;
        const float inv1 = 1.0f / tot1;

        // ---- store normalized O (this warp's d-half) ----
        float* or0 = outp + ((size_t)(b * SEQ + gi0)) * DIM + h * 64 + 2 * ac;
        float* or1 = or0 + 8 * DIM;
        #pragma unroll
        for (int nb = 0; nb < 8; nb++) {
            *(float2*)(or0 + nb * 8) = make_float2(Oa[nb][0] * inv0, Oa[nb][1] * inv0);
            *(float2*)(or1 + nb * 8) = make_float2(Oa[nb][2] * inv1, Oa[nb][3] * inv1);
        }

        // ---- in-kernel finalize: rescale own rows, cols [i0, SEQ) ----
        {
            const int W1 = (SEQ - i0) / 4;
            for (int row = wid; row < TILE; row += 16) {
                const float inv = 1.0f / (sL[row] + sL[128 + row]);
                float4* wr = (float4*)(wts + ((size_t)(b * SEQ + i0 + row)) * SEQ + i0);
                for (int q = l; q < W1; q += 32) {
                    float4 w = wr[q];
                    w.x *= inv; w.y *= inv; w.z *= inv; w.w *= inv;
                    wr[q] = w;
                }
            }
        }
    }
}

extern "C" void kernel_launch(void* const* d_in, const int* in_sizes, int n_in,
                              void* d_out, int out_size) {
    const float* Q = (const float*)d_in[0];
    const float* K = (const float*)d_in[1];
    const float* V = (const float*)d_in[2];
    float* outp = (float*)d_out;
    float* wts  = outp + (size_t)BATCH * SEQ * DIM;   // tuple: (outputs, weights)

    // pre-split Q/K/V into bf16 hi/lo
    dim3 pgrid(NELEM / 4 / 256, 3);
    split_pre_kernel<<<pgrid, 256>>>(Q, K, V);

    cudaFuncSetAttribute(attn_mma_kernel,
                         cudaFuncAttributeMaxDynamicSharedMemorySize, SMEM_BYTES);
    dim3 grid(NT / 2, BATCH);
    attn_mma_kernel<<<grid, 512, SMEM_BYTES>>>(outp, wts);
}